// round 13
// baseline (speedup 1.0000x reference)
#include <cuda_runtime.h>

// ---------------------------------------------------------------------------
// Fused 2-layer LSTM (H=50, D=1) + FC, B=2048, T=512, fp32.   R12.
//
// thread = (hid-pair hp in [0,25), batch-pair bg in [0,7), k-half ks in {0,1})
// -> 350 live threads (352 launched, 11 full warps), grid = 147.
//
// The 2hid x 2batch tile minimizes L1TEX instructions (the measured binder:
// step_cyc ~ 3 x warp-meminsts/SM), and the k-split restores 11 warps for
// latency hiding (R10 had the same inst count but only 5.5 warps -> 36% of
// step time was exposed latency). Partner threads (lane^1) hold the two
// k-halves of the same 16 gate sums; they combine via 16 shfl_xor butterflies
// per layer (shuffle does NOT touch the L1TEX crossbar). Activations split
// by hid: thread's own hid = 2*hp + ks.
//
//  * Weights: prepacked __device__ global 16B chunks [kp][chunk][hid], rows
//    padded to CW=64 entries; L1-resident.
//  * h: smem u64 (h_2kp, h_2kp+1) words, row stride 27 u64; the {kp, kp+12}
//    ks-split read pattern stays bank-conflict-free.
//  * All dot products: packed fma.rn.f32x2 over k-pairs.
// ---------------------------------------------------------------------------

#define HN      50
#define KP      25
#define TN      512
#define BATCHN  2048
#define NB      14
#define NTH     352             // 11 full warps; tids 350,351 compute-only
#define NGRID   147
#define HS      27              // u64 row stride for h buffers
#define CW      64              // chunk row width (entries, padded 50->64)

typedef unsigned long long u64;

// Prepacked weights (written by prepack_kernel each launch).
// g_w0[(kp*2+c)*CW + hid]: c0 = gates (i,f) k-pair, c1 = (g,o).     (Whh0)
// g_w1[(kp*4+c)*CW + hid]: c0,1 = Wih1 (i,f),(g,o); c2,3 = Whh1.
__device__ ulonglong2 g_w0[KP * 2 * CW];    //  51 KB
__device__ ulonglong2 g_w1[KP * 4 * CW];    // 102 KB

__device__ __forceinline__ void fma2(u64& d, u64 a, u64 b) {
    asm("fma.rn.f32x2 %0, %1, %2, %0;" : "+l"(d) : "l"(a), "l"(b));
}
__device__ __forceinline__ float hsum2(u64 v) {
    float lo, hi;
    asm("mov.b64 {%0, %1}, %2;" : "=f"(lo), "=f"(hi) : "l"(v));
    return lo + hi;
}
__device__ __forceinline__ float sig_f(float v) {
    return __fdividef(1.0f, 1.0f + __expf(-v));
}
__device__ __forceinline__ float tanh_f(float v) {
    return 1.0f - __fdividef(2.0f, 1.0f + __expf(2.0f * v));
}

__global__ void prepack_kernel(const float* __restrict__ Whh0,
                               const float* __restrict__ Wih1,
                               const float* __restrict__ Whh1)
{
    const int i = blockIdx.x * blockDim.x + threadIdx.x;
    if (i < KP * 2 * HN) {
        const int hid = i % HN, r = i / HN;
        const int c = r % 2, kp = r / 2;
        const int g0 = c * 2, g1 = g0 + 1, k0 = 2 * kp;
        float4 v;
        v.x = Whh0[(g0 * HN + hid) * HN + k0];
        v.y = Whh0[(g0 * HN + hid) * HN + k0 + 1];
        v.z = Whh0[(g1 * HN + hid) * HN + k0];
        v.w = Whh0[(g1 * HN + hid) * HN + k0 + 1];
        reinterpret_cast<float4*>(g_w0)[(kp * 2 + c) * CW + hid] = v;
    }
    if (i < KP * 4 * HN) {
        const int hid = i % HN, r = i / HN;
        const int c = r % 4, kp = r / 4;
        const int mat = c >> 1, sub = c & 1;
        const int g0 = sub * 2, g1 = g0 + 1, k0 = 2 * kp;
        const float* W = mat ? Whh1 : Wih1;
        float4 v;
        v.x = W[(g0 * HN + hid) * HN + k0];
        v.y = W[(g0 * HN + hid) * HN + k0 + 1];
        v.z = W[(g1 * HN + hid) * HN + k0];
        v.w = W[(g1 * HN + hid) * HN + k0 + 1];
        reinterpret_cast<float4*>(g_w1)[(kp * 4 + c) * CW + hid] = v;
    }
}

// Layer-0 accumulation body for one k-pair.
#define L0_BODY(kp_)                                                          \
    {                                                                         \
        const int kp = (kp_);                                                 \
        const ulonglong2 wif0 = w0a[(kp * 2 + 0) * CW];                       \
        const ulonglong2 wgo0 = w0a[(kp * 2 + 1) * CW];                       \
        const ulonglong2 wif1 = w0b[(kp * 2 + 0) * CW];                       \
        const ulonglong2 wgo1 = w0b[(kp * 2 + 1) * CW];                       \
        const u64 ha = h0s[rb][lb0][kp];                                      \
        const u64 hb = h0s[rb][lb1][kp];                                      \
        fma2(P[0][0][0], wif0.x, ha); fma2(P[0][1][0], wif0.y, ha);           \
        fma2(P[0][2][0], wgo0.x, ha); fma2(P[0][3][0], wgo0.y, ha);           \
        fma2(P[1][0][0], wif1.x, ha); fma2(P[1][1][0], wif1.y, ha);           \
        fma2(P[1][2][0], wgo1.x, ha); fma2(P[1][3][0], wgo1.y, ha);           \
        fma2(P[0][0][1], wif0.x, hb); fma2(P[0][1][1], wif0.y, hb);           \
        fma2(P[0][2][1], wgo0.x, hb); fma2(P[0][3][1], wgo0.y, hb);           \
        fma2(P[1][0][1], wif1.x, hb); fma2(P[1][1][1], wif1.y, hb);           \
        fma2(P[1][2][1], wgo1.x, hb); fma2(P[1][3][1], wgo1.y, hb);           \
    }

// Layer-1 accumulation body for one k-pair.
#define L1_BODY(kp_)                                                          \
    {                                                                         \
        const int kp = (kp_);                                                 \
        const ulonglong2 aif0 = w1a[(kp * 4 + 0) * CW];                       \
        const ulonglong2 ago0 = w1a[(kp * 4 + 1) * CW];                       \
        const ulonglong2 rif0 = w1a[(kp * 4 + 2) * CW];                       \
        const ulonglong2 rgo0 = w1a[(kp * 4 + 3) * CW];                       \
        const ulonglong2 aif1 = w1b[(kp * 4 + 0) * CW];                       \
        const ulonglong2 ago1 = w1b[(kp * 4 + 1) * CW];                       \
        const ulonglong2 rif1 = w1b[(kp * 4 + 2) * CW];                       \
        const ulonglong2 rgo1 = w1b[(kp * 4 + 3) * CW];                       \
        const u64 pa = h0s[wb][lb0][kp];                                      \
        const u64 pb = h0s[wb][lb1][kp];                                      \
        const u64 qa = h1s[rb][lb0][kp];                                      \
        const u64 qb = h1s[rb][lb1][kp];                                      \
        fma2(P[0][0][0], aif0.x, pa); fma2(P[0][1][0], aif0.y, pa);           \
        fma2(P[0][2][0], ago0.x, pa); fma2(P[0][3][0], ago0.y, pa);           \
        fma2(P[0][0][0], rif0.x, qa); fma2(P[0][1][0], rif0.y, qa);           \
        fma2(P[0][2][0], rgo0.x, qa); fma2(P[0][3][0], rgo0.y, qa);           \
        fma2(P[1][0][0], aif1.x, pa); fma2(P[1][1][0], aif1.y, pa);           \
        fma2(P[1][2][0], ago1.x, pa); fma2(P[1][3][0], ago1.y, pa);           \
        fma2(P[1][0][0], rif1.x, qa); fma2(P[1][1][0], rif1.y, qa);           \
        fma2(P[1][2][0], rgo1.x, qa); fma2(P[1][3][0], rgo1.y, qa);           \
        fma2(P[0][0][1], aif0.x, pb); fma2(P[0][1][1], aif0.y, pb);           \
        fma2(P[0][2][1], ago0.x, pb); fma2(P[0][3][1], ago0.y, pb);           \
        fma2(P[0][0][1], rif0.x, qb); fma2(P[0][1][1], rif0.y, qb);           \
        fma2(P[0][2][1], rgo0.x, qb); fma2(P[0][3][1], rgo0.y, qb);           \
        fma2(P[1][0][1], aif1.x, pb); fma2(P[1][1][1], aif1.y, pb);           \
        fma2(P[1][2][1], ago1.x, pb); fma2(P[1][3][1], ago1.y, pb);           \
        fma2(P[1][0][1], rif1.x, qb); fma2(P[1][1][1], rif1.y, qb);           \
        fma2(P[1][2][1], rgo1.x, qb); fma2(P[1][3][1], rgo1.y, qb);           \
    }

__global__ __launch_bounds__(NTH, 1)
void lstm_fused_kernel(const float* __restrict__ x,      // [B,T,1]
                       const float* __restrict__ Wih0,   // [200,1]
                       const float* __restrict__ bih0,   // [200]
                       const float* __restrict__ bhh0,   // [200]
                       const float* __restrict__ bih1,   // [200]
                       const float* __restrict__ bhh1,   // [200]
                       const float* __restrict__ Wfc,    // [2,50]
                       const float* __restrict__ bfc,    // [2]
                       float* __restrict__ out)          // [B,2]
{
    __shared__ u64 h0s[2][NB][HS];
    __shared__ u64 h1s[2][NB][HS];
    __shared__ float4 bias0s[HN], bias1s[HN], wx0s[HN];
    __shared__ float wfc_s[2 * HN];
    __shared__ float bfc_s[2];

    const int tid = threadIdx.x;

    // ------- stage biases / x-weights / fc into shared -------
    for (int hid = tid; hid < HN; hid += NTH) {
        bias0s[hid] = make_float4(bih0[0 * HN + hid] + bhh0[0 * HN + hid],
                                  bih0[1 * HN + hid] + bhh0[1 * HN + hid],
                                  bih0[2 * HN + hid] + bhh0[2 * HN + hid],
                                  bih0[3 * HN + hid] + bhh0[3 * HN + hid]);
        bias1s[hid] = make_float4(bih1[0 * HN + hid] + bhh1[0 * HN + hid],
                                  bih1[1 * HN + hid] + bhh1[1 * HN + hid],
                                  bih1[2 * HN + hid] + bhh1[2 * HN + hid],
                                  bih1[3 * HN + hid] + bhh1[3 * HN + hid]);
        wx0s[hid] = make_float4(Wih0[0 * HN + hid], Wih0[1 * HN + hid],
                                Wih0[2 * HN + hid], Wih0[3 * HN + hid]);
    }
    for (int i = tid; i < 2 * HN; i += NTH) wfc_s[i] = Wfc[i];
    if (tid < 2) bfc_s[tid] = bfc[tid];
    for (int i = tid; i < NB * HS; i += NTH) {      // zero buffer 0 (t=0 read)
        (&h0s[0][0][0])[i] = 0ull;
        (&h1s[0][0][0])[i] = 0ull;
    }
    __syncthreads();

    // ------- per-thread identity -------
    const bool alive = (tid < 350);
    const int ks  = tid & 1;                       // k-half
    const int bg  = (tid >> 1) % 7;                // batch pair
    const int hpr = tid / 14;
    const int hp  = (hpr < 25) ? hpr : 24;         // clamp tids 350,351
    const int hidm = 2 * hp + ks;                  // the hid this thread owns
    const int lb0 = 2 * bg, lb1 = lb0 + 1;
    const int b0 = blockIdx.x * NB + lb0;
    const int b1 = b0 + 1;
    const long xo0 = (long)(b0 < BATCHN ? b0 : BATCHN - 1) * TN;
    const long xo1 = (long)(b1 < BATCHN ? b1 : BATCHN - 1) * TN;

    const float4 bA = bias0s[hidm];
    const float4 bB = bias1s[hidm];
    const float4 wx = wx0s[hidm];

    const ulonglong2* __restrict__ w0a = g_w0 + 2 * hp;       // hid0 chunks
    const ulonglong2* __restrict__ w0b = g_w0 + 2 * hp + 1;   // hid1 chunks
    const ulonglong2* __restrict__ w1a = g_w1 + 2 * hp;
    const ulonglong2* __restrict__ w1b = g_w1 + 2 * hp + 1;

    // k-split: ks=0 covers kp {0..11, 24}; ks=1 covers kp {12..23}
    const int kb = ks * 12;

    float* const hf = reinterpret_cast<float*>(&h0s[0][0][0]);
    float* const hf1 = reinterpret_cast<float*>(&h1s[0][0][0]);
    const int ROWF = HS * 2;            // floats per batch row
    const int BUFF = NB * ROWF;         // floats per buffer

    float c0a = 0.f, c0b = 0.f;         // my hid's layer-0 cells (2 batches)
    float c1a = 0.f, c1b = 0.f;         // layer-1 cells

    float xa = x[xo0];
    float xb = x[xo1];

#pragma unroll 1
    for (int t = 0; t < TN; ++t) {
        const int rb = t & 1;
        const int wb = rb ^ 1;

        const int tn = (t + 1 < TN) ? (t + 1) : (TN - 1);
        const float xan = x[xo0 + tn];
        const float xbn = x[xo1 + tn];

        // ================= layer 0: partial gate sums over my k-half ======
        u64 P[2][4][2];
#pragma unroll
        for (int h = 0; h < 2; ++h)
#pragma unroll
            for (int g = 0; g < 4; ++g)
#pragma unroll
                for (int b = 0; b < 2; ++b) P[h][g][b] = 0ull;

#pragma unroll 4
        for (int i = 0; i < 12; ++i) L0_BODY(kb + i)
        if (ks == 0) L0_BODY(24)

        // combine k-halves with partner (lane^1), keep my hid's totals
        float T[4][2];
#pragma unroll
        for (int g = 0; g < 4; ++g)
#pragma unroll
            for (int b = 0; b < 2; ++b) {
                const float p0 = hsum2(P[0][g][b]);
                const float p1 = hsum2(P[1][g][b]);
                const float s0 = p0 + __shfl_xor_sync(0xffffffffu, p0, 1);
                const float s1 = p1 + __shfl_xor_sync(0xffffffffu, p1, 1);
                T[g][b] = ks ? s1 : s0;
            }

        float h0a, h0b;
        {
            const float Ai = T[0][0] + __fmaf_rn(wx.x, xa, bA.x);
            const float Af = T[1][0] + __fmaf_rn(wx.y, xa, bA.y);
            const float Ag = T[2][0] + __fmaf_rn(wx.z, xa, bA.z);
            const float Ao = T[3][0] + __fmaf_rn(wx.w, xa, bA.w);
            const float i_ = sig_f(Ai), f_ = sig_f(Af);
            const float g_ = tanh_f(Ag), o_ = sig_f(Ao);
            c0a = f_ * c0a + i_ * g_;
            h0a = o_ * tanh_f(c0a);
        }
        {
            const float Ai = T[0][1] + __fmaf_rn(wx.x, xb, bA.x);
            const float Af = T[1][1] + __fmaf_rn(wx.y, xb, bA.y);
            const float Ag = T[2][1] + __fmaf_rn(wx.z, xb, bA.z);
            const float Ao = T[3][1] + __fmaf_rn(wx.w, xb, bA.w);
            const float i_ = sig_f(Ai), f_ = sig_f(Af);
            const float g_ = tanh_f(Ag), o_ = sig_f(Ao);
            c0b = f_ * c0b + i_ * g_;
            h0b = o_ * tanh_f(c0b);
        }
        if (alive) {
            hf[wb * BUFF + lb0 * ROWF + hidm] = h0a;
            hf[wb * BUFF + lb1 * ROWF + hidm] = h0b;
        }
        __syncthreads();

        // ================= layer 1 =================
#pragma unroll
        for (int h = 0; h < 2; ++h)
#pragma unroll
            for (int g = 0; g < 4; ++g)
#pragma unroll
                for (int b = 0; b < 2; ++b) P[h][g][b] = 0ull;

#pragma unroll 4
        for (int i = 0; i < 12; ++i) L1_BODY(kb + i)
        if (ks == 0) L1_BODY(24)

#pragma unroll
        for (int g = 0; g < 4; ++g)
#pragma unroll
            for (int b = 0; b < 2; ++b) {
                const float p0 = hsum2(P[0][g][b]);
                const float p1 = hsum2(P[1][g][b]);
                const float s0 = p0 + __shfl_xor_sync(0xffffffffu, p0, 1);
                const float s1 = p1 + __shfl_xor_sync(0xffffffffu, p1, 1);
                T[g][b] = ks ? s1 : s0;
            }

        float h1a, h1b;
        {
            const float Ai = T[0][0] + bB.x;
            const float Af = T[1][0] + bB.y;
            const float Ag = T[2][0] + bB.z;
            const float Ao = T[3][0] + bB.w;
            const float i_ = sig_f(Ai), f_ = sig_f(Af);
            const float g_ = tanh_f(Ag), o_ = sig_f(Ao);
            c1a = f_ * c1a + i_ * g_;
            h1a = o_ * tanh_f(c1a);
        }
        {
            const float Ai = T[0][1] + bB.x;
            const float Af = T[1][1] + bB.y;
            const float Ag = T[2][1] + bB.z;
            const float Ao = T[3][1] + bB.w;
            const float i_ = sig_f(Ai), f_ = sig_f(Af);
            const float g_ = tanh_f(Ag), o_ = sig_f(Ao);
            c1b = f_ * c1b + i_ * g_;
            h1b = o_ * tanh_f(c1b);
        }
        if (alive) {
            hf1[wb * BUFF + lb0 * ROWF + hidm] = h1a;
            hf1[wb * BUFF + lb1 * ROWF + hidm] = h1b;
        }
        __syncthreads();

        xa = xan;
        xb = xbn;
    }

    // ---- final FC: out[b,c] = h1_last[b,:] . Wfc[c,:] + bfc[c] ----
    const int FB = TN & 1;   // buffer holding h1 at t=T-1 (=0 for even T)
    if (tid < NB * 2) {
        const int pb = tid >> 1;
        const int cc = tid & 1;
        const int b = blockIdx.x * NB + pb;
        if (b < BATCHN) {
            float acc = bfc_s[cc];
#pragma unroll
            for (int kp = 0; kp < KP; ++kp) {
                const u64 hpair = h1s[FB][pb][kp];
                float lo, hi;
                asm("mov.b64 {%0, %1}, %2;" : "=f"(lo), "=f"(hi) : "l"(hpair));
                acc += lo * wfc_s[cc * HN + 2 * kp]
                     + hi * wfc_s[cc * HN + 2 * kp + 1];
            }
            out[b * 2 + cc] = acc;
        }
    }
}

extern "C" void kernel_launch(void* const* d_in, const int* in_sizes, int n_in,
                              void* d_out, int out_size)
{
    (void)in_sizes; (void)n_in; (void)out_size;

    const float* x    = (const float*)d_in[0];
    const float* Wih0 = (const float*)d_in[1];
    const float* Whh0 = (const float*)d_in[2];
    const float* bih0 = (const float*)d_in[3];
    const float* bhh0 = (const float*)d_in[4];
    const float* Wih1 = (const float*)d_in[5];
    const float* Whh1 = (const float*)d_in[6];
    const float* bih1 = (const float*)d_in[7];
    const float* bhh1 = (const float*)d_in[8];
    const float* Wfc  = (const float*)d_in[9];
    const float* bfc  = (const float*)d_in[10];

    prepack_kernel<<<(KP * 4 * HN + 255) / 256, 256>>>(Whh0, Wih1, Whh1);

    lstm_fused_kernel<<<NGRID, NTH>>>(
        x, Wih0, bih0, bhh0, bih1, bhh1, Wfc, bfc, (float*)d_out);
}